// round 1
// baseline (speedup 1.0000x reference)
#include <cuda_runtime.h>
#include <math.h>

// Problem constants (hardcoded: B=8, H=W=64, C=512, nh=16, hd=32, ss=8)
#define M_TOT 32768        // B*H*W
#define K_DIM 512          // C
#define QKV_N 1536         // 3*C

// SGEMM tiling
#define BM 128
#define BN 128
#define BK 16
#define TM 8
#define TN 8

// Scratch (allocation-free rule: __device__ globals)
__device__ __align__(16) float g_qkv[(size_t)M_TOT * QKV_N];   // 192 MB: q|k|v per row
__device__ __align__(16) float g_attn[(size_t)M_TOT * K_DIM];  // 64 MB: concat(out_h, out_v)

// ---------------------------------------------------------------------------
// Tiled FP32 SGEMM: C[m][n] = sum_k A[m][k] * B[n][k] (+ bias[n])
// A: M_TOT x K_DIM row-major, B: N x K_DIM row-major. M_TOT%128==0, N%128==0, K%16==0.
// ---------------------------------------------------------------------------
template <int N, bool HAS_BIAS>
__device__ __forceinline__ void sgemm_nt_body(const float* __restrict__ A,
                                              const float* __restrict__ B,
                                              const float* __restrict__ bias,
                                              float* __restrict__ C) {
    __shared__ float As[BK][BM + 4];
    __shared__ float Bs[BK][BN + 4];

    const int tid = threadIdx.x;          // 0..255
    const int tx = tid & 15;              // 0..15
    const int ty = tid >> 4;              // 0..15
    const int m0 = blockIdx.y * BM;
    const int n0 = blockIdx.x * BN;

    const int lr = tid >> 2;              // 0..63  load row
    const int lc = (tid & 3) << 2;        // 0,4,8,12 load k-col (float4)

    float acc[TM][TN];
    #pragma unroll
    for (int i = 0; i < TM; i++)
        #pragma unroll
        for (int j = 0; j < TN; j++) acc[i][j] = 0.f;

    for (int k0 = 0; k0 < K_DIM; k0 += BK) {
        const float4 a0 = *(const float4*)&A[(size_t)(m0 + lr) * K_DIM + k0 + lc];
        const float4 a1 = *(const float4*)&A[(size_t)(m0 + lr + 64) * K_DIM + k0 + lc];
        const float4 b0 = *(const float4*)&B[(size_t)(n0 + lr) * K_DIM + k0 + lc];
        const float4 b1 = *(const float4*)&B[(size_t)(n0 + lr + 64) * K_DIM + k0 + lc];

        __syncthreads();   // previous iteration's reads done before overwrite
        As[lc + 0][lr] = a0.x; As[lc + 1][lr] = a0.y; As[lc + 2][lr] = a0.z; As[lc + 3][lr] = a0.w;
        As[lc + 0][lr + 64] = a1.x; As[lc + 1][lr + 64] = a1.y; As[lc + 2][lr + 64] = a1.z; As[lc + 3][lr + 64] = a1.w;
        Bs[lc + 0][lr] = b0.x; Bs[lc + 1][lr] = b0.y; Bs[lc + 2][lr] = b0.z; Bs[lc + 3][lr] = b0.w;
        Bs[lc + 0][lr + 64] = b1.x; Bs[lc + 1][lr + 64] = b1.y; Bs[lc + 2][lr + 64] = b1.z; Bs[lc + 3][lr + 64] = b1.w;
        __syncthreads();

        #pragma unroll
        for (int kk = 0; kk < BK; kk++) {
            float am[TM], bn[TN];
            *(float4*)&am[0] = *(const float4*)&As[kk][ty * TM];
            *(float4*)&am[4] = *(const float4*)&As[kk][ty * TM + 4];
            *(float4*)&bn[0] = *(const float4*)&Bs[kk][tx * TN];
            *(float4*)&bn[4] = *(const float4*)&Bs[kk][tx * TN + 4];
            #pragma unroll
            for (int i = 0; i < TM; i++)
                #pragma unroll
                for (int j = 0; j < TN; j++)
                    acc[i][j] = fmaf(am[i], bn[j], acc[i][j]);
        }
    }

    #pragma unroll
    for (int i = 0; i < TM; i++) {
        const int m = m0 + ty * TM + i;
        #pragma unroll
        for (int j4 = 0; j4 < TN; j4 += 4) {
            const int n = n0 + tx * TN + j4;
            float4 r;
            if (HAS_BIAS) {
                r.x = acc[i][j4 + 0] + bias[n + 0];
                r.y = acc[i][j4 + 1] + bias[n + 1];
                r.z = acc[i][j4 + 2] + bias[n + 2];
                r.w = acc[i][j4 + 3] + bias[n + 3];
            } else {
                r.x = acc[i][j4 + 0]; r.y = acc[i][j4 + 1];
                r.z = acc[i][j4 + 2]; r.w = acc[i][j4 + 3];
            }
            *(float4*)&C[(size_t)m * N + n] = r;
        }
    }
}

__global__ void __launch_bounds__(256, 2)
qkv_gemm_kernel(const float* __restrict__ x, const float* __restrict__ w_qkv) {
    sgemm_nt_body<QKV_N, false>(x, w_qkv, nullptr, g_qkv);
}

__global__ void __launch_bounds__(256, 2)
proj_gemm_kernel(const float* __restrict__ w_proj, const float* __restrict__ b_proj,
                 float* __restrict__ out) {
    sgemm_nt_body<K_DIM, true>(g_attn, w_proj, b_proj, out);
}

// ---------------------------------------------------------------------------
// Fused stripe attention + LePE.
// Grid: 8192 blocks. block < 4096 -> axis 0 (horizontal stripes, channels 0..255)
//                    block >=4096 -> axis 1 (vertical stripes,  channels 256..511)
// 256 threads = channel within half. Each block: one (b, stripe, orth-pos) window,
// 8 tokens x 8 heads x hd 32.
// ---------------------------------------------------------------------------
__global__ void __launch_bounds__(256, 4)
attn_kernel(const float* __restrict__ lepe_h, const float* __restrict__ lepe_v) {
    __shared__ float qs[8][257];
    __shared__ float ks[8][257];
    __shared__ float vs[8][257];
    __shared__ float S[8][8][8];   // [head][i][j]

    const int bidx = blockIdx.x;
    const int axis = bidx >> 12;       // 0 or 1
    const int rem  = bidx & 4095;
    const int b    = rem >> 9;         // /512
    const int r    = rem & 511;

    int tok_m[8];
    if (axis == 0) {
        const int s = r >> 6;          // stripe along H
        const int w = r & 63;
        #pragma unroll
        for (int i = 0; i < 8; i++) tok_m[i] = (b << 12) + ((s * 8 + i) << 6) + w;
    } else {
        const int h = r >> 3;
        const int s = r & 7;           // stripe along W
        #pragma unroll
        for (int i = 0; i < 8; i++) tok_m[i] = (b << 12) + (h << 6) + (s * 8 + i);
    }

    const int c_local = threadIdx.x;            // 0..255
    const int c = (axis << 8) + c_local;        // global channel

    // Stage q/k/v for the window
    #pragma unroll
    for (int i = 0; i < 8; i++) {
        const float* base = &g_qkv[(size_t)tok_m[i] * QKV_N + c];
        qs[i][c_local] = base[0];
        ks[i][c_local] = base[512];
        vs[i][c_local] = base[1024];
    }
    __syncthreads();

    // Scores: 8 heads x 8x8 = 512 entries, 2 per thread
    const float inv_scale = 0.17677669529663688f;  // 1/sqrt(32)
    #pragma unroll
    for (int e = 0; e < 2; e++) {
        const int idx = threadIdx.x + (e << 8);
        const int hh = idx >> 6;
        const int i = (idx >> 3) & 7;
        const int j = idx & 7;
        const int cb = hh << 5;
        float sum = 0.f;
        #pragma unroll
        for (int d = 0; d < 32; d++) sum = fmaf(qs[i][cb + d], ks[j][cb + d], sum);
        S[hh][i][j] = sum * inv_scale;
    }
    __syncthreads();

    // Softmax over j (64 rows of 8)
    if (threadIdx.x < 64) {
        const int hh = threadIdx.x >> 3;
        const int i = threadIdx.x & 7;
        float* row = S[hh][i];
        float mx = row[0];
        #pragma unroll
        for (int j = 1; j < 8; j++) mx = fmaxf(mx, row[j]);
        float ex[8], sum = 0.f;
        #pragma unroll
        for (int j = 0; j < 8; j++) { ex[j] = __expf(row[j] - mx); sum += ex[j]; }
        const float inv = 1.f / sum;
        #pragma unroll
        for (int j = 0; j < 8; j++) row[j] = ex[j] * inv;
    }
    __syncthreads();

    // Output: attn @ v + depthwise-3x3 LePE(v)
    const int head = c_local >> 5;
    const float* lw = (axis == 0) ? lepe_h : lepe_v;  // (3,3,1,256), channel idx = c_local
    float wgt[9];
    #pragma unroll
    for (int t = 0; t < 9; t++) wgt[t] = lw[t * 256 + c_local];

    #pragma unroll
    for (int i = 0; i < 8; i++) {
        float acc = 0.f;
        #pragma unroll
        for (int j = 0; j < 8; j++) acc = fmaf(S[head][i][j], vs[j][c_local], acc);

        const int m = tok_m[i];
        const int bb = m >> 12;
        const int h = (m >> 6) & 63;
        const int w = m & 63;
        float lep = 0.f;
        #pragma unroll
        for (int dh = -1; dh <= 1; dh++) {
            #pragma unroll
            for (int dw = -1; dw <= 1; dw++) {
                const int h2 = h + dh, w2 = w + dw;
                if (h2 >= 0 && h2 < 64 && w2 >= 0 && w2 < 64) {
                    const float vv = g_qkv[(size_t)((bb << 12) + (h2 << 6) + w2) * QKV_N + 1024 + c];
                    lep = fmaf(vv, wgt[(dh + 1) * 3 + (dw + 1)], lep);
                }
            }
        }
        g_attn[(size_t)m * K_DIM + c] = acc + lep;
    }
}

// ---------------------------------------------------------------------------
extern "C" void kernel_launch(void* const* d_in, const int* in_sizes, int n_in,
                              void* d_out, int out_size) {
    (void)in_sizes; (void)n_in; (void)out_size;
    const float* x      = (const float*)d_in[0];  // (8, 4096, 512)
    const float* w_qkv  = (const float*)d_in[1];  // (1536, 512)
    const float* w_proj = (const float*)d_in[2];  // (512, 512)
    const float* b_proj = (const float*)d_in[3];  // (512,)
    const float* lepe_h = (const float*)d_in[4];  // (3,3,1,256)
    const float* lepe_v = (const float*)d_in[5];  // (3,3,1,256)
    float* out = (float*)d_out;                   // (8, 4096, 512)

    dim3 blk(256);
    qkv_gemm_kernel<<<dim3(QKV_N / BN, M_TOT / BM), blk>>>(x, w_qkv);
    attn_kernel<<<8192, blk>>>(lepe_h, lepe_v);
    proj_gemm_kernel<<<dim3(K_DIM / BN, M_TOT / BM), blk>>>(w_proj, b_proj, out);
}

// round 2
// speedup vs baseline: 1.2536x; 1.2536x over previous
#include <cuda_runtime.h>
#include <math.h>
#include <stdint.h>

// Problem constants (B=8, H=W=64, C=512, nh=16, hd=32, ss=8)
#define M_TOT 32768
#define K_DIM 512
#define QKV_N 1536

// Scratch (allocation-free rule: __device__ globals)
__device__ __align__(16) float g_qkv[(size_t)M_TOT * QKV_N];   // q|k|v per row
__device__ __align__(16) float g_attn[(size_t)M_TOT * K_DIM];  // concat(out_h, out_v)

// ---------------------------------------------------------------------------
// 3xTF32 tensor-core GEMM: C[m][n] = sum_k A[m][k]*B[n][k] (+bias[n])
// A: M x K row-major, B: N x K row-major (NT). BM=BN=128, BK=16.
// 8 warps, warp tile 64x32 (4 m16 x 4 n8 mma tiles), mma.sync.m16n8k8.tf32.
// Each fp32 value x is split hi=tf32(x), lo=tf32(x-hi); D += Ahi*Bhi + Alo*Bhi
// + Ahi*Blo  (error ~2^-21, far inside the 1e-3 budget).
// ---------------------------------------------------------------------------
#define BM 128
#define BN 128
#define BK 16
#define BKP 20   // padded row stride (floats): 20*g+t is conflict-free over 32 banks

__device__ __forceinline__ float to_tf32(float x) {
    uint32_t u;
    asm("cvt.rna.tf32.f32 %0, %1;" : "=r"(u) : "f"(x));
    return __uint_as_float(u);
}

__device__ __forceinline__ void mma_tf32(float (&d)[4], const float (&a)[4], const float (&b)[2]) {
    const uint32_t* A = reinterpret_cast<const uint32_t*>(a);
    const uint32_t* B = reinterpret_cast<const uint32_t*>(b);
    asm volatile(
        "mma.sync.aligned.m16n8k8.row.col.f32.tf32.tf32.f32 "
        "{%0,%1,%2,%3}, {%4,%5,%6,%7}, {%8,%9}, {%0,%1,%2,%3};"
        : "+f"(d[0]), "+f"(d[1]), "+f"(d[2]), "+f"(d[3])
        : "r"(A[0]), "r"(A[1]), "r"(A[2]), "r"(A[3]), "r"(B[0]), "r"(B[1]));
}

template <int N, bool HAS_BIAS>
__device__ __forceinline__ void tf32_gemm_body(const float* __restrict__ A,
                                               const float* __restrict__ B,
                                               const float* __restrict__ bias,
                                               float* __restrict__ C) {
    __shared__ float As_hi[BM][BKP];
    __shared__ float As_lo[BM][BKP];
    __shared__ float Bs_hi[BN][BKP];
    __shared__ float Bs_lo[BN][BKP];

    const int tid  = threadIdx.x;
    const int warp = tid >> 5;
    const int lane = tid & 31;
    const int wm = warp & 1;        // 2 warps along M
    const int wn = warp >> 1;       // 4 warps along N
    const int g = lane >> 2;        // group id 0..7
    const int t = lane & 3;         // thread-in-group 0..3

    const int m0 = blockIdx.y * BM;
    const int n0 = blockIdx.x * BN;

    const int lr = tid >> 2;            // 0..63
    const int lc = (tid & 3) << 2;      // 0,4,8,12

    float acc[4][4][4];
    #pragma unroll
    for (int i = 0; i < 4; i++)
        #pragma unroll
        for (int j = 0; j < 4; j++)
            #pragma unroll
            for (int r = 0; r < 4; r++) acc[i][j][r] = 0.f;

    for (int k0 = 0; k0 < K_DIM; k0 += BK) {
        const float4 a0 = *(const float4*)&A[(size_t)(m0 + lr) * K_DIM + k0 + lc];
        const float4 a1 = *(const float4*)&A[(size_t)(m0 + lr + 64) * K_DIM + k0 + lc];
        const float4 b0 = *(const float4*)&B[(size_t)(n0 + lr) * K_DIM + k0 + lc];
        const float4 b1 = *(const float4*)&B[(size_t)(n0 + lr + 64) * K_DIM + k0 + lc];

        __syncthreads();
        {
            const float av0[4] = {a0.x, a0.y, a0.z, a0.w};
            const float av1[4] = {a1.x, a1.y, a1.z, a1.w};
            const float bv0[4] = {b0.x, b0.y, b0.z, b0.w};
            const float bv1[4] = {b1.x, b1.y, b1.z, b1.w};
            float4 h, l;
            #define SPLIT4(src, H, L)                                     \
                H.x = to_tf32(src[0]); L.x = to_tf32(src[0] - H.x);       \
                H.y = to_tf32(src[1]); L.y = to_tf32(src[1] - H.y);       \
                H.z = to_tf32(src[2]); L.z = to_tf32(src[2] - H.z);       \
                H.w = to_tf32(src[3]); L.w = to_tf32(src[3] - H.w);
            SPLIT4(av0, h, l);
            *(float4*)&As_hi[lr][lc] = h;      *(float4*)&As_lo[lr][lc] = l;
            SPLIT4(av1, h, l);
            *(float4*)&As_hi[lr + 64][lc] = h; *(float4*)&As_lo[lr + 64][lc] = l;
            SPLIT4(bv0, h, l);
            *(float4*)&Bs_hi[lr][lc] = h;      *(float4*)&Bs_lo[lr][lc] = l;
            SPLIT4(bv1, h, l);
            *(float4*)&Bs_hi[lr + 64][lc] = h; *(float4*)&Bs_lo[lr + 64][lc] = l;
            #undef SPLIT4
        }
        __syncthreads();

        #pragma unroll
        for (int ks = 0; ks < BK; ks += 8) {
            // B fragments for this warp's 4 n8 tiles
            float bh[4][2], bl[4][2];
            #pragma unroll
            for (int nt = 0; nt < 4; nt++) {
                const int n = wn * 32 + nt * 8 + g;
                bh[nt][0] = Bs_hi[n][ks + t];
                bh[nt][1] = Bs_hi[n][ks + t + 4];
                bl[nt][0] = Bs_lo[n][ks + t];
                bl[nt][1] = Bs_lo[n][ks + t + 4];
            }
            #pragma unroll
            for (int mt = 0; mt < 4; mt++) {
                const int m = wm * 64 + mt * 16 + g;
                float ah[4], al[4];
                ah[0] = As_hi[m][ks + t];     ah[1] = As_hi[m + 8][ks + t];
                ah[2] = As_hi[m][ks + t + 4]; ah[3] = As_hi[m + 8][ks + t + 4];
                al[0] = As_lo[m][ks + t];     al[1] = As_lo[m + 8][ks + t];
                al[2] = As_lo[m][ks + t + 4]; al[3] = As_lo[m + 8][ks + t + 4];
                #pragma unroll
                for (int nt = 0; nt < 4; nt++) {
                    mma_tf32(acc[mt][nt], ah, bh[nt]);   // hi*hi
                    mma_tf32(acc[mt][nt], al, bh[nt]);   // lo*hi
                    mma_tf32(acc[mt][nt], ah, bl[nt]);   // hi*lo
                }
            }
        }
    }

    // Epilogue: c0/c1 at (g, 2t/2t+1), c2/c3 at (g+8, same cols)
    #pragma unroll
    for (int mt = 0; mt < 4; mt++) {
        #pragma unroll
        for (int nt = 0; nt < 4; nt++) {
            const int m = m0 + wm * 64 + mt * 16 + g;
            const int n = n0 + wn * 32 + nt * 8 + 2 * t;
            float2 r0 = make_float2(acc[mt][nt][0], acc[mt][nt][1]);
            float2 r1 = make_float2(acc[mt][nt][2], acc[mt][nt][3]);
            if (HAS_BIAS) {
                const float bz0 = bias[n], bz1 = bias[n + 1];
                r0.x += bz0; r0.y += bz1;
                r1.x += bz0; r1.y += bz1;
            }
            *(float2*)&C[(size_t)m * N + n] = r0;
            *(float2*)&C[(size_t)(m + 8) * N + n] = r1;
        }
    }
}

__global__ void __launch_bounds__(256, 2)
qkv_gemm_kernel(const float* __restrict__ x, const float* __restrict__ w_qkv) {
    tf32_gemm_body<QKV_N, false>(x, w_qkv, nullptr, g_qkv);
}

__global__ void __launch_bounds__(256, 2)
proj_gemm_kernel(const float* __restrict__ w_proj, const float* __restrict__ b_proj,
                 float* __restrict__ out) {
    tf32_gemm_body<K_DIM, true>(g_attn, w_proj, b_proj, out);
}

// ---------------------------------------------------------------------------
// Fused stripe attention + LePE (unchanged from R1; ~100us, not the bottleneck)
// ---------------------------------------------------------------------------
__global__ void __launch_bounds__(256, 4)
attn_kernel(const float* __restrict__ lepe_h, const float* __restrict__ lepe_v) {
    __shared__ float qs[8][257];
    __shared__ float ks[8][257];
    __shared__ float vs[8][257];
    __shared__ float S[8][8][8];   // [head][i][j]

    const int bidx = blockIdx.x;
    const int axis = bidx >> 12;
    const int rem  = bidx & 4095;
    const int b    = rem >> 9;
    const int r    = rem & 511;

    int tok_m[8];
    if (axis == 0) {
        const int s = r >> 6;
        const int w = r & 63;
        #pragma unroll
        for (int i = 0; i < 8; i++) tok_m[i] = (b << 12) + ((s * 8 + i) << 6) + w;
    } else {
        const int h = r >> 3;
        const int s = r & 7;
        #pragma unroll
        for (int i = 0; i < 8; i++) tok_m[i] = (b << 12) + (h << 6) + (s * 8 + i);
    }

    const int c_local = threadIdx.x;
    const int c = (axis << 8) + c_local;

    #pragma unroll
    for (int i = 0; i < 8; i++) {
        const float* base = &g_qkv[(size_t)tok_m[i] * QKV_N + c];
        qs[i][c_local] = base[0];
        ks[i][c_local] = base[512];
        vs[i][c_local] = base[1024];
    }
    __syncthreads();

    const float inv_scale = 0.17677669529663688f;  // 1/sqrt(32)
    #pragma unroll
    for (int e = 0; e < 2; e++) {
        const int idx = threadIdx.x + (e << 8);
        const int hh = idx >> 6;
        const int i = (idx >> 3) & 7;
        const int j = idx & 7;
        const int cb = hh << 5;
        float sum = 0.f;
        #pragma unroll
        for (int d = 0; d < 32; d++) sum = fmaf(qs[i][cb + d], ks[j][cb + d], sum);
        S[hh][i][j] = sum * inv_scale;
    }
    __syncthreads();

    if (threadIdx.x < 64) {
        const int hh = threadIdx.x >> 3;
        const int i = threadIdx.x & 7;
        float* row = S[hh][i];
        float mx = row[0];
        #pragma unroll
        for (int j = 1; j < 8; j++) mx = fmaxf(mx, row[j]);
        float ex[8], sum = 0.f;
        #pragma unroll
        for (int j = 0; j < 8; j++) { ex[j] = __expf(row[j] - mx); sum += ex[j]; }
        const float inv = 1.f / sum;
        #pragma unroll
        for (int j = 0; j < 8; j++) row[j] = ex[j] * inv;
    }
    __syncthreads();

    const int head = c_local >> 5;
    const float* lw = (axis == 0) ? lepe_h : lepe_v;
    float wgt[9];
    #pragma unroll
    for (int tt = 0; tt < 9; tt++) wgt[tt] = lw[tt * 256 + c_local];

    #pragma unroll
    for (int i = 0; i < 8; i++) {
        float acc = 0.f;
        #pragma unroll
        for (int j = 0; j < 8; j++) acc = fmaf(S[head][i][j], vs[j][c_local], acc);

        const int m = tok_m[i];
        const int bb = m >> 12;
        const int h = (m >> 6) & 63;
        const int w = m & 63;
        float lep = 0.f;
        #pragma unroll
        for (int dh = -1; dh <= 1; dh++) {
            #pragma unroll
            for (int dw = -1; dw <= 1; dw++) {
                const int h2 = h + dh, w2 = w + dw;
                if (h2 >= 0 && h2 < 64 && w2 >= 0 && w2 < 64) {
                    const float vv = g_qkv[(size_t)((bb << 12) + (h2 << 6) + w2) * QKV_N + 1024 + c];
                    lep = fmaf(vv, wgt[(dh + 1) * 3 + (dw + 1)], lep);
                }
            }
        }
        g_attn[(size_t)m * K_DIM + c] = acc + lep;
    }
}

// ---------------------------------------------------------------------------
extern "C" void kernel_launch(void* const* d_in, const int* in_sizes, int n_in,
                              void* d_out, int out_size) {
    (void)in_sizes; (void)n_in; (void)out_size;
    const float* x      = (const float*)d_in[0];  // (8, 4096, 512)
    const float* w_qkv  = (const float*)d_in[1];  // (1536, 512)
    const float* w_proj = (const float*)d_in[2];  // (512, 512)
    const float* b_proj = (const float*)d_in[3];  // (512,)
    const float* lepe_h = (const float*)d_in[4];  // (3,3,1,256)
    const float* lepe_v = (const float*)d_in[5];  // (3,3,1,256)
    float* out = (float*)d_out;                   // (8, 4096, 512)

    dim3 blk(256);
    qkv_gemm_kernel<<<dim3(QKV_N / BN, M_TOT / BM), blk>>>(x, w_qkv);
    attn_kernel<<<8192, blk>>>(lepe_h, lepe_v);
    proj_gemm_kernel<<<dim3(K_DIM / BN, M_TOT / BM), blk>>>(w_proj, b_proj, out);
}

// round 4
// speedup vs baseline: 1.8028x; 1.4381x over previous
#include <cuda_runtime.h>
#include <cuda_fp16.h>
#include <math.h>
#include <stdint.h>

// Problem constants (B=8, H=W=64, C=512, nh=16, hd=32, ss=8)
#define M_TOT 32768
#define K_DIM 512
#define QKV_N 1536

// Scratch (allocation-free rule: __device__ globals)
__device__ __align__(16) float g_qkv[(size_t)M_TOT * QKV_N];   // q|k|v per row
__device__ __align__(16) float g_attn[(size_t)M_TOT * K_DIM];  // concat(out_h, out_v)

// ---------------------------------------------------------------------------
// 3xFP16 tensor-core GEMM: C[m][n] = sum_k A[m][k]*B[n][k] (+bias[n])
// A: M x K row-major, B: N x K row-major (NT). BM=BN=128, BK=32.
// 8 warps, warp tile 64x32 (4 m16 x 4 n8), mma.sync.m16n8k16.f16 (fp32 acc).
// x = hi + lo with hi=f16(x), lo=f16(x-hi); D += Ah*Bh + Al*Bh + Ah*Bl.
// Per-product error ~2^-22 -> rel_err ~1e-5 (budget 1e-3).
// ---------------------------------------------------------------------------
#define BM 128
#define BN 128
#define BK 32
#define RS 20   // smem row stride in u32 (16 half2 data + 4 pad): 20*g+t conflict-free

__device__ __forceinline__ uint32_t pack_hi(float f0, float f1, uint32_t& lo) {
    const __half h0 = __float2half_rn(f0);
    const __half h1 = __float2half_rn(f1);
    const __half l0 = __float2half_rn(f0 - __half2float(h0));
    const __half l1 = __float2half_rn(f1 - __half2float(h1));
    lo = (uint32_t)__half_as_ushort(l0) | ((uint32_t)__half_as_ushort(l1) << 16);
    return (uint32_t)__half_as_ushort(h0) | ((uint32_t)__half_as_ushort(h1) << 16);
}

__device__ __forceinline__ void mma_f16(float (&d)[4], const uint32_t (&a)[4],
                                        const uint32_t (&b)[2]) {
    asm volatile(
        "mma.sync.aligned.m16n8k16.row.col.f32.f16.f16.f32 "
        "{%0,%1,%2,%3}, {%4,%5,%6,%7}, {%8,%9}, {%0,%1,%2,%3};"
        : "+f"(d[0]), "+f"(d[1]), "+f"(d[2]), "+f"(d[3])
        : "r"(a[0]), "r"(a[1]), "r"(a[2]), "r"(a[3]), "r"(b[0]), "r"(b[1]));
}

template <int N, bool HAS_BIAS>
__device__ __forceinline__ void f16_gemm_body(const float* __restrict__ A,
                                              const float* __restrict__ B,
                                              const float* __restrict__ bias,
                                              float* __restrict__ C) {
    // u32 = half2; row stride RS
    __shared__ uint32_t Ah[BM * RS];
    __shared__ uint32_t Al[BM * RS];
    __shared__ uint32_t Bh[BN * RS];
    __shared__ uint32_t Bl[BN * RS];

    const int tid  = threadIdx.x;
    const int warp = tid >> 5;
    const int lane = tid & 31;
    const int wm = warp & 1;        // 2 warps along M (64 rows each)
    const int wn = warp >> 1;       // 4 warps along N (32 cols each)
    const int g = lane >> 2;        // 0..7
    const int t = lane & 3;         // 0..3

    const int m0 = blockIdx.y * BM;
    const int n0 = blockIdx.x * BN;

    const int lr = tid >> 2;              // 0..63 (rows lr and lr+64)
    const int cb = (tid & 3) << 3;        // 0,8,16,24 col block (8 floats)

    float acc[4][4][4];
    #pragma unroll
    for (int i = 0; i < 4; i++)
        #pragma unroll
        for (int j = 0; j < 4; j++)
            #pragma unroll
            for (int r = 0; r < 4; r++) acc[i][j][r] = 0.f;

    for (int k0 = 0; k0 < K_DIM; k0 += BK) {
        // Global loads (2 float4 per row segment, 4 segments/thread)
        float4 ga[4], gb[4];
        {
            const float* a0 = &A[(size_t)(m0 + lr) * K_DIM + k0 + cb];
            const float* a1 = &A[(size_t)(m0 + lr + 64) * K_DIM + k0 + cb];
            const float* b0 = &B[(size_t)(n0 + lr) * K_DIM + k0 + cb];
            const float* b1 = &B[(size_t)(n0 + lr + 64) * K_DIM + k0 + cb];
            ga[0] = *(const float4*)a0; ga[1] = *(const float4*)(a0 + 4);
            ga[2] = *(const float4*)a1; ga[3] = *(const float4*)(a1 + 4);
            gb[0] = *(const float4*)b0; gb[1] = *(const float4*)(b0 + 4);
            gb[2] = *(const float4*)b1; gb[3] = *(const float4*)(b1 + 4);
        }

        __syncthreads();   // previous iteration's fragment reads done
        {
            const int c2 = cb >> 1;  // half2 col index: 0,4,8,12
            #pragma unroll
            for (int seg = 0; seg < 2; seg++) {   // rows lr, lr+64
                const int r = lr + seg * 64;
                uint4 hi, lo;
                hi.x = pack_hi(ga[2 * seg].x, ga[2 * seg].y, lo.x);
                hi.y = pack_hi(ga[2 * seg].z, ga[2 * seg].w, lo.y);
                hi.z = pack_hi(ga[2 * seg + 1].x, ga[2 * seg + 1].y, lo.z);
                hi.w = pack_hi(ga[2 * seg + 1].z, ga[2 * seg + 1].w, lo.w);
                *(uint4*)&Ah[r * RS + c2] = hi;
                *(uint4*)&Al[r * RS + c2] = lo;
                hi.x = pack_hi(gb[2 * seg].x, gb[2 * seg].y, lo.x);
                hi.y = pack_hi(gb[2 * seg].z, gb[2 * seg].w, lo.y);
                hi.z = pack_hi(gb[2 * seg + 1].x, gb[2 * seg + 1].y, lo.z);
                hi.w = pack_hi(gb[2 * seg + 1].z, gb[2 * seg + 1].w, lo.w);
                *(uint4*)&Bh[r * RS + c2] = hi;
                *(uint4*)&Bl[r * RS + c2] = lo;
            }
        }
        __syncthreads();

        #pragma unroll
        for (int ks = 0; ks < 2; ks++) {          // two k16 steps
            const int k2 = ks * 8;                // half2 base index
            uint32_t bh[4][2], bl[4][2];
            #pragma unroll
            for (int nt = 0; nt < 4; nt++) {
                const int n = wn * 32 + nt * 8 + g;
                bh[nt][0] = Bh[n * RS + k2 + t];
                bh[nt][1] = Bh[n * RS + k2 + t + 4];
                bl[nt][0] = Bl[n * RS + k2 + t];
                bl[nt][1] = Bl[n * RS + k2 + t + 4];
            }
            #pragma unroll
            for (int mt = 0; mt < 4; mt++) {
                const int m = wm * 64 + mt * 16 + g;
                uint32_t ah[4], al[4];
                ah[0] = Ah[m * RS + k2 + t];
                ah[1] = Ah[(m + 8) * RS + k2 + t];
                ah[2] = Ah[m * RS + k2 + t + 4];
                ah[3] = Ah[(m + 8) * RS + k2 + t + 4];
                al[0] = Al[m * RS + k2 + t];
                al[1] = Al[(m + 8) * RS + k2 + t];
                al[2] = Al[m * RS + k2 + t + 4];
                al[3] = Al[(m + 8) * RS + k2 + t + 4];
                #pragma unroll
                for (int nt = 0; nt < 4; nt++) {
                    mma_f16(acc[mt][nt], ah, bh[nt]);   // hi*hi
                    mma_f16(acc[mt][nt], al, bh[nt]);   // lo*hi
                    mma_f16(acc[mt][nt], ah, bl[nt]);   // hi*lo
                }
            }
        }
    }

    // Epilogue: c0/c1 at (g, 2t..2t+1), c2/c3 at (g+8, same cols)
    #pragma unroll
    for (int mt = 0; mt < 4; mt++) {
        #pragma unroll
        for (int nt = 0; nt < 4; nt++) {
            const int m = m0 + wm * 64 + mt * 16 + g;
            const int n = n0 + wn * 32 + nt * 8 + 2 * t;
            float2 r0 = make_float2(acc[mt][nt][0], acc[mt][nt][1]);
            float2 r1 = make_float2(acc[mt][nt][2], acc[mt][nt][3]);
            if (HAS_BIAS) {
                const float bz0 = bias[n], bz1 = bias[n + 1];
                r0.x += bz0; r0.y += bz1;
                r1.x += bz0; r1.y += bz1;
            }
            *(float2*)&C[(size_t)m * N + n] = r0;
            *(float2*)&C[(size_t)(m + 8) * N + n] = r1;
        }
    }
}

__global__ void __launch_bounds__(256, 2)
qkv_gemm_kernel(const float* __restrict__ x, const float* __restrict__ w_qkv) {
    f16_gemm_body<QKV_N, false>(x, w_qkv, nullptr, g_qkv);
}

__global__ void __launch_bounds__(256, 2)
proj_gemm_kernel(const float* __restrict__ w_proj, const float* __restrict__ b_proj,
                 float* __restrict__ out) {
    f16_gemm_body<K_DIM, true>(g_attn, w_proj, b_proj, out);
}

// ---------------------------------------------------------------------------
// Fused stripe attention + LePE (unchanged; ~90us)
// ---------------------------------------------------------------------------
__global__ void __launch_bounds__(256, 4)
attn_kernel(const float* __restrict__ lepe_h, const float* __restrict__ lepe_v) {
    __shared__ float qs[8][257];
    __shared__ float ks[8][257];
    __shared__ float vs[8][257];
    __shared__ float S[8][8][8];

    const int bidx = blockIdx.x;
    const int axis = bidx >> 12;
    const int rem  = bidx & 4095;
    const int b    = rem >> 9;
    const int r    = rem & 511;

    int tok_m[8];
    if (axis == 0) {
        const int s = r >> 6;
        const int w = r & 63;
        #pragma unroll
        for (int i = 0; i < 8; i++) tok_m[i] = (b << 12) + ((s * 8 + i) << 6) + w;
    } else {
        const int h = r >> 3;
        const int s = r & 7;
        #pragma unroll
        for (int i = 0; i < 8; i++) tok_m[i] = (b << 12) + (h << 6) + (s * 8 + i);
    }

    const int c_local = threadIdx.x;
    const int c = (axis << 8) + c_local;

    #pragma unroll
    for (int i = 0; i < 8; i++) {
        const float* base = &g_qkv[(size_t)tok_m[i] * QKV_N + c];
        qs[i][c_local] = base[0];
        ks[i][c_local] = base[512];
        vs[i][c_local] = base[1024];
    }
    __syncthreads();

    const float inv_scale = 0.17677669529663688f;  // 1/sqrt(32)
    #pragma unroll
    for (int e = 0; e < 2; e++) {
        const int idx = threadIdx.x + (e << 8);
        const int hh = idx >> 6;
        const int i = (idx >> 3) & 7;
        const int j = idx & 7;
        const int cbh = hh << 5;
        float sum = 0.f;
        #pragma unroll
        for (int d = 0; d < 32; d++) sum = fmaf(qs[i][cbh + d], ks[j][cbh + d], sum);
        S[hh][i][j] = sum * inv_scale;
    }
    __syncthreads();

    if (threadIdx.x < 64) {
        const int hh = threadIdx.x >> 3;
        const int i = threadIdx.x & 7;
        float* row = S[hh][i];
        float mx = row[0];
        #pragma unroll
        for (int j = 1; j < 8; j++) mx = fmaxf(mx, row[j]);
        float ex[8], sum = 0.f;
        #pragma unroll
        for (int j = 0; j < 8; j++) { ex[j] = __expf(row[j] - mx); sum += ex[j]; }
        const float inv = 1.f / sum;
        #pragma unroll
        for (int j = 0; j < 8; j++) row[j] = ex[j] * inv;
    }
    __syncthreads();

    const int head = c_local >> 5;
    const float* lw = (axis == 0) ? lepe_h : lepe_v;
    float wgt[9];
    #pragma unroll
    for (int tt = 0; tt < 9; tt++) wgt[tt] = lw[tt * 256 + c_local];

    #pragma unroll
    for (int i = 0; i < 8; i++) {
        float acc = 0.f;
        #pragma unroll
        for (int j = 0; j < 8; j++) acc = fmaf(S[head][i][j], vs[j][c_local], acc);

        const int m = tok_m[i];
        const int bb = m >> 12;
        const int h = (m >> 6) & 63;
        const int w = m & 63;
        float lep = 0.f;
        #pragma unroll
        for (int dh = -1; dh <= 1; dh++) {
            #pragma unroll
            for (int dw = -1; dw <= 1; dw++) {
                const int h2 = h + dh, w2 = w + dw;
                if (h2 >= 0 && h2 < 64 && w2 >= 0 && w2 < 64) {
                    const float vv = g_qkv[(size_t)((bb << 12) + (h2 << 6) + w2) * QKV_N + 1024 + c];
                    lep = fmaf(vv, wgt[(dh + 1) * 3 + (dw + 1)], lep);
                }
            }
        }
        g_attn[(size_t)m * K_DIM + c] = acc + lep;
    }
}

// ---------------------------------------------------------------------------
extern "C" void kernel_launch(void* const* d_in, const int* in_sizes, int n_in,
                              void* d_out, int out_size) {
    (void)in_sizes; (void)n_in; (void)out_size;
    const float* x      = (const float*)d_in[0];  // (8, 4096, 512)
    const float* w_qkv  = (const float*)d_in[1];  // (1536, 512)
    const float* w_proj = (const float*)d_in[2];  // (512, 512)
    const float* b_proj = (const float*)d_in[3];  // (512,)
    const float* lepe_h = (const float*)d_in[4];  // (3,3,1,256)
    const float* lepe_v = (const float*)d_in[5];  // (3,3,1,256)
    float* out = (float*)d_out;                   // (8, 4096, 512)

    dim3 blk(256);
    qkv_gemm_kernel<<<dim3(QKV_N / BN, M_TOT / BM), blk>>>(x, w_qkv);
    attn_kernel<<<8192, blk>>>(lepe_h, lepe_v);
    proj_gemm_kernel<<<dim3(K_DIM / BN, M_TOT / BM), blk>>>(w_proj, b_proj, out);
}

// round 5
// speedup vs baseline: 2.5410x; 1.4095x over previous
#include <cuda_runtime.h>
#include <cuda_fp16.h>
#include <math.h>
#include <stdint.h>

// Problem constants (B=8, H=W=64, C=512, nh=16, hd=32, ss=8)
#define M_TOT 32768
#define K_DIM 512
#define QKV_N 1536

// Scratch (allocation-free rule: __device__ globals)
__device__ __align__(16) float  g_qkv[(size_t)M_TOT * QKV_N];   // q|k|v fp32 (attn input)
__device__ __align__(16) __half g_xh[(size_t)M_TOT * K_DIM];    // x hi
__device__ __align__(16) __half g_xl[(size_t)M_TOT * K_DIM];    // x lo
__device__ __align__(16) __half g_ah[(size_t)M_TOT * K_DIM];    // attn-out hi
__device__ __align__(16) __half g_al[(size_t)M_TOT * K_DIM];    // attn-out lo
__device__ __align__(16) __half g_wqh[(size_t)QKV_N * K_DIM];   // w_qkv hi
__device__ __align__(16) __half g_wph[(size_t)K_DIM * K_DIM];   // w_proj hi

// ---------------------------------------------------------------------------
// Helpers
// ---------------------------------------------------------------------------
__device__ __forceinline__ uint32_t smem_u32(const void* p) {
    uint32_t a;
    asm("{ .reg .u64 t; cvta.to.shared.u64 t, %1; cvt.u32.u64 %0, t; }" : "=r"(a) : "l"(p));
    return a;
}
__device__ __forceinline__ void cp16(uint32_t dst, const void* src) {
    asm volatile("cp.async.cg.shared.global [%0], [%1], 16;"
                 :: "r"(dst), "l"(__cvta_generic_to_global(src)));
}
__device__ __forceinline__ void cp_commit() { asm volatile("cp.async.commit_group;"); }
__device__ __forceinline__ void ldm4(uint32_t (&r)[4], uint32_t addr) {
    asm volatile("ldmatrix.sync.aligned.m8n8.x4.shared.b16 {%0,%1,%2,%3}, [%4];"
                 : "=r"(r[0]), "=r"(r[1]), "=r"(r[2]), "=r"(r[3]) : "r"(addr));
}
__device__ __forceinline__ void mma_f16(float (&d)[4], const uint32_t (&a)[4],
                                        uint32_t b0, uint32_t b1) {
    asm volatile(
        "mma.sync.aligned.m16n8k16.row.col.f32.f16.f16.f32 "
        "{%0,%1,%2,%3}, {%4,%5,%6,%7}, {%8,%9}, {%0,%1,%2,%3};"
        : "+f"(d[0]), "+f"(d[1]), "+f"(d[2]), "+f"(d[3])
        : "r"(a[0]), "r"(a[1]), "r"(a[2]), "r"(a[3]), "r"(b0), "r"(b1));
}

// ---------------------------------------------------------------------------
// Split fp32 -> fp16 hi (+ optional lo). 4 floats per thread.
// ---------------------------------------------------------------------------
__global__ void __launch_bounds__(256)
split_kernel(const float* __restrict__ src, __half* __restrict__ hi,
             __half* __restrict__ lo, int n4) {
    const int i = blockIdx.x * blockDim.x + threadIdx.x;
    if (i >= n4) return;
    const float4 f = ((const float4*)src)[i];
    const __half h0 = __float2half_rn(f.x), h1 = __float2half_rn(f.y);
    const __half h2 = __float2half_rn(f.z), h3 = __float2half_rn(f.w);
    ((__half2*)hi)[2 * i]     = __halves2half2(h0, h1);
    ((__half2*)hi)[2 * i + 1] = __halves2half2(h2, h3);
    if (lo != nullptr) {
        ((__half2*)lo)[2 * i]     = __halves2half2(__float2half_rn(f.x - __half2float(h0)),
                                                   __float2half_rn(f.y - __half2float(h1)));
        ((__half2*)lo)[2 * i + 1] = __halves2half2(__float2half_rn(f.z - __half2float(h2)),
                                                   __float2half_rn(f.w - __half2float(h3)));
    }
}

// ---------------------------------------------------------------------------
// 2-term fp16 tensor GEMM: C = (Ah+Al) * Bh^T (+bias). A hi/lo and B hi are
// pre-split fp16 in gmem (M x K / N x K row-major).
// BM=BN=128, BK=32, 8 warps (warp tile 64x32), cp.async double buffer,
// ldmatrix fragments. Row stride 80B -> ldmatrix conflict-free.
// ---------------------------------------------------------------------------
#define BK 32
#define RS_B 80                        // smem row stride, bytes (64 data + 16 pad)
#define TILE_BYTES (128 * RS_B)        // 10240
#define STAGE_BYTES (3 * TILE_BYTES)   // Ah | Al | Bh
#define SMEM_DYN (2 * STAGE_BYTES)     // 61440
#define NCH (K_DIM / BK)               // 16

template <int N, bool HAS_BIAS>
__device__ __forceinline__ void gemm2_body(const __half* __restrict__ Ah_g,
                                           const __half* __restrict__ Al_g,
                                           const __half* __restrict__ Bh_g,
                                           const float* __restrict__ bias,
                                           float* __restrict__ C) {
    extern __shared__ __align__(16) char smem[];
    const uint32_t sbase = smem_u32(smem);

    const int tid = threadIdx.x;
    const int warp = tid >> 5;
    const int lane = tid & 31;
    const int wm = warp & 1;        // 2 warps along M
    const int wn = warp >> 1;       // 4 warps along N
    const int g = lane >> 2;
    const int t = lane & 3;

    const int m0 = blockIdx.y * 128;
    const int n0 = blockIdx.x * 128;

    // cp.async assignment: row = tid>>1 (0..127), two 16B chunks at c16 = (tid&1)*2, +1
    const int crow = tid >> 1;
    const int cc = (tid & 1) * 2;
    const __half* a_src = Ah_g + (size_t)(m0 + crow) * K_DIM + cc * 8;
    const __half* l_src = Al_g + (size_t)(m0 + crow) * K_DIM + cc * 8;
    const __half* b_src = Bh_g + (size_t)(n0 + crow) * K_DIM + cc * 8;
    const uint32_t cdst = sbase + crow * RS_B + cc * 16;

    // Per-lane ldmatrix base offsets
    const uint32_t aRow = (uint32_t)(wm * 64 + (lane & 15)) * RS_B + ((lane >> 4) << 4);
    const uint32_t bRow = (uint32_t)(wn * 32 + (lane & 7) + ((lane >> 4) << 3)) * RS_B +
                          (((lane >> 3) & 1) << 4);

    float acc[4][4][4];
    #pragma unroll
    for (int i = 0; i < 4; i++)
        #pragma unroll
        for (int j = 0; j < 4; j++)
            #pragma unroll
            for (int r = 0; r < 4; r++) acc[i][j][r] = 0.f;

    // Prologue: stage 0 <- chunk 0
    {
        cp16(cdst, a_src);                            cp16(cdst + 16, a_src + 8);
        cp16(cdst + TILE_BYTES, l_src);               cp16(cdst + TILE_BYTES + 16, l_src + 8);
        cp16(cdst + 2 * TILE_BYTES, b_src);           cp16(cdst + 2 * TILE_BYTES + 16, b_src + 8);
        cp_commit();
    }

    for (int ch = 0; ch < NCH; ch++) {
        const int s = ch & 1;
        if (ch + 1 < NCH) {
            const int ko = (ch + 1) * BK;
            const uint32_t d = cdst + ((ch + 1) & 1) * STAGE_BYTES;
            cp16(d, a_src + ko);                      cp16(d + 16, a_src + ko + 8);
            cp16(d + TILE_BYTES, l_src + ko);         cp16(d + TILE_BYTES + 16, l_src + ko + 8);
            cp16(d + 2 * TILE_BYTES, b_src + ko);     cp16(d + 2 * TILE_BYTES + 16, b_src + ko + 8);
            cp_commit();
            asm volatile("cp.async.wait_group 1;");
        } else {
            asm volatile("cp.async.wait_group 0;");
        }
        __syncthreads();

        const uint32_t sA  = sbase + s * STAGE_BYTES;
        const uint32_t sAl = sA + TILE_BYTES;
        const uint32_t sB  = sA + 2 * TILE_BYTES;

        #pragma unroll
        for (int ks = 0; ks < 2; ks++) {
            uint32_t b0[4], b1[4];
            ldm4(b0, sB + bRow + ks * 32);                    // n tiles 0,1 of this warp
            ldm4(b1, sB + bRow + 16 * RS_B + ks * 32);        // n tiles 2,3
            #pragma unroll
            for (int mt = 0; mt < 4; mt++) {
                uint32_t ah[4], al[4];
                ldm4(ah, sA  + aRow + mt * 16 * RS_B + ks * 32);
                ldm4(al, sAl + aRow + mt * 16 * RS_B + ks * 32);
                mma_f16(acc[mt][0], ah, b0[0], b0[1]);
                mma_f16(acc[mt][1], ah, b0[2], b0[3]);
                mma_f16(acc[mt][2], ah, b1[0], b1[1]);
                mma_f16(acc[mt][3], ah, b1[2], b1[3]);
                mma_f16(acc[mt][0], al, b0[0], b0[1]);
                mma_f16(acc[mt][1], al, b0[2], b0[3]);
                mma_f16(acc[mt][2], al, b1[0], b1[1]);
                mma_f16(acc[mt][3], al, b1[2], b1[3]);
            }
        }
        __syncthreads();
    }

    // Epilogue: c0/c1 at (g, 2t..2t+1), c2/c3 at (g+8, same cols)
    #pragma unroll
    for (int mt = 0; mt < 4; mt++) {
        #pragma unroll
        for (int nt = 0; nt < 4; nt++) {
            const int m = m0 + wm * 64 + mt * 16 + g;
            const int n = n0 + wn * 32 + nt * 8 + 2 * t;
            float2 r0 = make_float2(acc[mt][nt][0], acc[mt][nt][1]);
            float2 r1 = make_float2(acc[mt][nt][2], acc[mt][nt][3]);
            if (HAS_BIAS) {
                const float bz0 = bias[n], bz1 = bias[n + 1];
                r0.x += bz0; r0.y += bz1;
                r1.x += bz0; r1.y += bz1;
            }
            *(float2*)&C[(size_t)m * N + n] = r0;
            *(float2*)&C[(size_t)(m + 8) * N + n] = r1;
        }
    }
}

__global__ void __launch_bounds__(256, 2)
qkv_gemm_kernel() {
    gemm2_body<QKV_N, false>(g_xh, g_xl, g_wqh, nullptr, g_qkv);
}

__global__ void __launch_bounds__(256, 2)
proj_gemm_kernel(const float* __restrict__ b_proj, float* __restrict__ out) {
    gemm2_body<K_DIM, true>(g_ah, g_al, g_wph, b_proj, out);
}

// ---------------------------------------------------------------------------
// Fused stripe attention + LePE; writes output pre-split to fp16 hi/lo.
// ---------------------------------------------------------------------------
__global__ void __launch_bounds__(256, 4)
attn_kernel(const float* __restrict__ lepe_h, const float* __restrict__ lepe_v) {
    __shared__ float qs[8][257];
    __shared__ float ks[8][257];
    __shared__ float vs[8][257];
    __shared__ float S[8][8][8];

    const int bidx = blockIdx.x;
    const int axis = bidx >> 12;
    const int rem  = bidx & 4095;
    const int b    = rem >> 9;
    const int r    = rem & 511;

    int tok_m[8];
    if (axis == 0) {
        const int s = r >> 6;
        const int w = r & 63;
        #pragma unroll
        for (int i = 0; i < 8; i++) tok_m[i] = (b << 12) + ((s * 8 + i) << 6) + w;
    } else {
        const int h = r >> 3;
        const int s = r & 7;
        #pragma unroll
        for (int i = 0; i < 8; i++) tok_m[i] = (b << 12) + (h << 6) + (s * 8 + i);
    }

    const int c_local = threadIdx.x;
    const int c = (axis << 8) + c_local;

    #pragma unroll
    for (int i = 0; i < 8; i++) {
        const float* base = &g_qkv[(size_t)tok_m[i] * QKV_N + c];
        qs[i][c_local] = base[0];
        ks[i][c_local] = base[512];
        vs[i][c_local] = base[1024];
    }
    __syncthreads();

    const float inv_scale = 0.17677669529663688f;  // 1/sqrt(32)
    #pragma unroll
    for (int e = 0; e < 2; e++) {
        const int idx = threadIdx.x + (e << 8);
        const int hh = idx >> 6;
        const int i = (idx >> 3) & 7;
        const int j = idx & 7;
        const int cbh = hh << 5;
        float sum = 0.f;
        #pragma unroll
        for (int d = 0; d < 32; d++) sum = fmaf(qs[i][cbh + d], ks[j][cbh + d], sum);
        S[hh][i][j] = sum * inv_scale;
    }
    __syncthreads();

    if (threadIdx.x < 64) {
        const int hh = threadIdx.x >> 3;
        const int i = threadIdx.x & 7;
        float* row = S[hh][i];
        float mx = row[0];
        #pragma unroll
        for (int j = 1; j < 8; j++) mx = fmaxf(mx, row[j]);
        float ex[8], sum = 0.f;
        #pragma unroll
        for (int j = 0; j < 8; j++) { ex[j] = __expf(row[j] - mx); sum += ex[j]; }
        const float inv = 1.f / sum;
        #pragma unroll
        for (int j = 0; j < 8; j++) row[j] = ex[j] * inv;
    }
    __syncthreads();

    const int head = c_local >> 5;
    const float* lw = (axis == 0) ? lepe_h : lepe_v;
    float wgt[9];
    #pragma unroll
    for (int tt = 0; tt < 9; tt++) wgt[tt] = lw[tt * 256 + c_local];

    #pragma unroll
    for (int i = 0; i < 8; i++) {
        float acc = 0.f;
        #pragma unroll
        for (int j = 0; j < 8; j++) acc = fmaf(S[head][i][j], vs[j][c_local], acc);

        const int m = tok_m[i];
        const int bb = m >> 12;
        const int h = (m >> 6) & 63;
        const int w = m & 63;
        float lep = 0.f;
        #pragma unroll
        for (int dh = -1; dh <= 1; dh++) {
            #pragma unroll
            for (int dw = -1; dw <= 1; dw++) {
                const int h2 = h + dh, w2 = w + dw;
                if (h2 >= 0 && h2 < 64 && w2 >= 0 && w2 < 64) {
                    const float vv = g_qkv[(size_t)((bb << 12) + (h2 << 6) + w2) * QKV_N + 1024 + c];
                    lep = fmaf(vv, wgt[(dh + 1) * 3 + (dw + 1)], lep);
                }
            }
        }
        const float o = acc + lep;
        const __half oh = __float2half_rn(o);
        g_ah[(size_t)m * K_DIM + c] = oh;
        g_al[(size_t)m * K_DIM + c] = __float2half_rn(o - __half2float(oh));
    }
}

// ---------------------------------------------------------------------------
extern "C" void kernel_launch(void* const* d_in, const int* in_sizes, int n_in,
                              void* d_out, int out_size) {
    (void)in_sizes; (void)n_in; (void)out_size;
    const float* x      = (const float*)d_in[0];  // (8, 4096, 512)
    const float* w_qkv  = (const float*)d_in[1];  // (1536, 512)
    const float* w_proj = (const float*)d_in[2];  // (512, 512)
    const float* b_proj = (const float*)d_in[3];  // (512,)
    const float* lepe_h = (const float*)d_in[4];  // (3,3,1,256)
    const float* lepe_v = (const float*)d_in[5];  // (3,3,1,256)
    float* out = (float*)d_out;                   // (8, 4096, 512)

    static bool attr_set = false;
    if (!attr_set) {
        cudaFuncSetAttribute(qkv_gemm_kernel, cudaFuncAttributeMaxDynamicSharedMemorySize, SMEM_DYN);
        cudaFuncSetAttribute(proj_gemm_kernel, cudaFuncAttributeMaxDynamicSharedMemorySize, SMEM_DYN);
        attr_set = true;
    }

    __half* xh;  __half* xl;  __half* wqh; __half* wph;
    cudaGetSymbolAddress((void**)&xh,  g_xh);
    cudaGetSymbolAddress((void**)&xl,  g_xl);
    cudaGetSymbolAddress((void**)&wqh, g_wqh);
    cudaGetSymbolAddress((void**)&wph, g_wph);

    dim3 blk(256);
    split_kernel<<<(M_TOT * K_DIM / 4 + 255) / 256, blk>>>(x, xh, xl, M_TOT * K_DIM / 4);
    split_kernel<<<(QKV_N * K_DIM / 4 + 255) / 256, blk>>>(w_qkv, wqh, nullptr, QKV_N * K_DIM / 4);
    split_kernel<<<(K_DIM * K_DIM / 4 + 255) / 256, blk>>>(w_proj, wph, nullptr, K_DIM * K_DIM / 4);

    qkv_gemm_kernel<<<dim3(QKV_N / 128, M_TOT / 128), blk, SMEM_DYN>>>();
    attn_kernel<<<8192, blk>>>(lepe_h, lepe_v);
    proj_gemm_kernel<<<dim3(K_DIM / 128, M_TOT / 128), blk, SMEM_DYN>>>(b_proj, out);
}

// round 6
// speedup vs baseline: 3.4825x; 1.3705x over previous
#include <cuda_runtime.h>
#include <cuda_fp16.h>
#include <math.h>
#include <stdint.h>

// Problem constants (B=8, H=W=64, C=512, nh=16, hd=32, ss=8)
#define M_TOT 32768
#define K_DIM 512
#define QKV_N 1536

// Scratch (allocation-free rule: __device__ globals)
__device__ __align__(16) float  g_qkv[(size_t)M_TOT * QKV_N];   // q|k|v fp32 (attn input)
__device__ __align__(16) __half g_xh[(size_t)M_TOT * K_DIM];    // x hi
__device__ __align__(16) __half g_ah[(size_t)M_TOT * K_DIM];    // attn-out hi
__device__ __align__(16) __half g_al[(size_t)M_TOT * K_DIM];    // attn-out lo
__device__ __align__(16) __half g_wqh[(size_t)QKV_N * K_DIM];   // w_qkv hi
__device__ __align__(16) __half g_wph[(size_t)K_DIM * K_DIM];   // w_proj hi

// ---------------------------------------------------------------------------
// Helpers
// ---------------------------------------------------------------------------
__device__ __forceinline__ uint32_t smem_u32(const void* p) {
    uint32_t a;
    asm("{ .reg .u64 t; cvta.to.shared.u64 t, %1; cvt.u32.u64 %0, t; }" : "=r"(a) : "l"(p));
    return a;
}
__device__ __forceinline__ void cp16(uint32_t dst, const void* src) {
    asm volatile("cp.async.cg.shared.global [%0], [%1], 16;"
                 :: "r"(dst), "l"(__cvta_generic_to_global(src)));
}
__device__ __forceinline__ void cp_commit() { asm volatile("cp.async.commit_group;"); }
template <int Nwait>
__device__ __forceinline__ void cp_wait() {
    asm volatile("cp.async.wait_group %0;" :: "n"(Nwait));
}
__device__ __forceinline__ void ldm4(uint32_t (&r)[4], uint32_t addr) {
    asm volatile("ldmatrix.sync.aligned.m8n8.x4.shared.b16 {%0,%1,%2,%3}, [%4];"
                 : "=r"(r[0]), "=r"(r[1]), "=r"(r[2]), "=r"(r[3]) : "r"(addr));
}
__device__ __forceinline__ void mma_f16(float (&d)[4], const uint32_t (&a)[4],
                                        uint32_t b0, uint32_t b1) {
    asm volatile(
        "mma.sync.aligned.m16n8k16.row.col.f32.f16.f16.f32 "
        "{%0,%1,%2,%3}, {%4,%5,%6,%7}, {%8,%9}, {%0,%1,%2,%3};"
        : "+f"(d[0]), "+f"(d[1]), "+f"(d[2]), "+f"(d[3])
        : "r"(a[0]), "r"(a[1]), "r"(a[2]), "r"(a[3]), "r"(b0), "r"(b1));
}

// ---------------------------------------------------------------------------
// Split fp32 -> fp16 hi (+ optional lo).
// ---------------------------------------------------------------------------
__global__ void __launch_bounds__(256)
split_kernel(const float* __restrict__ src, __half* __restrict__ hi,
             __half* __restrict__ lo, int n4) {
    const int i = blockIdx.x * blockDim.x + threadIdx.x;
    if (i >= n4) return;
    const float4 f = ((const float4*)src)[i];
    const __half h0 = __float2half_rn(f.x), h1 = __float2half_rn(f.y);
    const __half h2 = __float2half_rn(f.z), h3 = __float2half_rn(f.w);
    ((__half2*)hi)[2 * i]     = __halves2half2(h0, h1);
    ((__half2*)hi)[2 * i + 1] = __halves2half2(h2, h3);
    if (lo != nullptr) {
        ((__half2*)lo)[2 * i]     = __halves2half2(__float2half_rn(f.x - __half2float(h0)),
                                                   __float2half_rn(f.y - __half2float(h1)));
        ((__half2*)lo)[2 * i + 1] = __halves2half2(__float2half_rn(f.z - __half2float(h2)),
                                                   __float2half_rn(f.w - __half2float(h3)));
    }
}

// ---------------------------------------------------------------------------
// fp16 tensor GEMM: C = (Ah [+Al]) * Bh^T (+bias), multi-stage cp.async.
// BM=BN=128, BK=32, 8 warps (warp tile 64x32), ldmatrix fragments,
// row stride 80B (conflict-free), one __syncthreads per chunk.
// ---------------------------------------------------------------------------
#define BK 32
#define RS_B 80
#define TILE_BYTES (128 * RS_B)   // 10240
#define NCH (K_DIM / BK)          // 16

template <int N, int TERMS, int NSTAGE, bool HAS_BIAS>
__device__ __forceinline__ void gemm_body(const __half* __restrict__ Ah_g,
                                          const __half* __restrict__ Al_g,
                                          const __half* __restrict__ Bh_g,
                                          const float* __restrict__ bias,
                                          float* __restrict__ C) {
    constexpr int STAGE_BYTES = (TERMS + 1) * TILE_BYTES;
    constexpr int B_OFF = TERMS * TILE_BYTES;

    extern __shared__ __align__(16) char smem[];
    const uint32_t sbase = smem_u32(smem);

    const int tid = threadIdx.x;
    const int warp = tid >> 5;
    const int lane = tid & 31;
    const int wm = warp & 1;
    const int wn = warp >> 1;
    const int g = lane >> 2;
    const int t = lane & 3;

    const int m0 = blockIdx.y * 128;
    const int n0 = blockIdx.x * 128;

    const int crow = tid >> 1;
    const int cc = (tid & 1) * 2;
    const __half* a_src = Ah_g + (size_t)(m0 + crow) * K_DIM + cc * 8;
    const __half* l_src = (TERMS == 2) ? (Al_g + (size_t)(m0 + crow) * K_DIM + cc * 8) : nullptr;
    const __half* b_src = Bh_g + (size_t)(n0 + crow) * K_DIM + cc * 8;
    const uint32_t cdst = sbase + crow * RS_B + cc * 16;

    const uint32_t aRow = (uint32_t)(wm * 64 + (lane & 15)) * RS_B + ((lane >> 4) << 4);
    const uint32_t bRow = (uint32_t)(wn * 32 + (lane & 7) + ((lane >> 4) << 3)) * RS_B +
                          (((lane >> 3) & 1) << 4);

    float acc[4][4][4];
    #pragma unroll
    for (int i = 0; i < 4; i++)
        #pragma unroll
        for (int j = 0; j < 4; j++)
            #pragma unroll
            for (int r = 0; r < 4; r++) acc[i][j][r] = 0.f;

    auto issue = [&](int ch) {
        if (ch < NCH) {
            const int ko = ch * BK;
            const uint32_t d = cdst + (uint32_t)(ch % NSTAGE) * STAGE_BYTES;
            cp16(d, a_src + ko);               cp16(d + 16, a_src + ko + 8);
            if (TERMS == 2) {
                cp16(d + TILE_BYTES, l_src + ko);
                cp16(d + TILE_BYTES + 16, l_src + ko + 8);
            }
            cp16(d + B_OFF, b_src + ko);       cp16(d + B_OFF + 16, b_src + ko + 8);
        }
        cp_commit();
    };

    #pragma unroll
    for (int s = 0; s < NSTAGE - 1; s++) issue(s);

    for (int ch = 0; ch < NCH; ch++) {
        cp_wait<NSTAGE - 2>();
        __syncthreads();
        issue(ch + NSTAGE - 1);

        const uint32_t sA = sbase + (uint32_t)(ch % NSTAGE) * STAGE_BYTES;
        const uint32_t sB = sA + B_OFF;

        #pragma unroll
        for (int ks = 0; ks < 2; ks++) {
            uint32_t b0[4], b1[4];
            ldm4(b0, sB + bRow + ks * 32);
            ldm4(b1, sB + bRow + 16 * RS_B + ks * 32);
            #pragma unroll
            for (int mt = 0; mt < 4; mt++) {
                uint32_t ah[4];
                ldm4(ah, sA + aRow + mt * 16 * RS_B + ks * 32);
                mma_f16(acc[mt][0], ah, b0[0], b0[1]);
                mma_f16(acc[mt][1], ah, b0[2], b0[3]);
                mma_f16(acc[mt][2], ah, b1[0], b1[1]);
                mma_f16(acc[mt][3], ah, b1[2], b1[3]);
                if (TERMS == 2) {
                    uint32_t al[4];
                    ldm4(al, sA + TILE_BYTES + aRow + mt * 16 * RS_B + ks * 32);
                    mma_f16(acc[mt][0], al, b0[0], b0[1]);
                    mma_f16(acc[mt][1], al, b0[2], b0[3]);
                    mma_f16(acc[mt][2], al, b1[0], b1[1]);
                    mma_f16(acc[mt][3], al, b1[2], b1[3]);
                }
            }
        }
    }

    #pragma unroll
    for (int mt = 0; mt < 4; mt++) {
        #pragma unroll
        for (int nt = 0; nt < 4; nt++) {
            const int m = m0 + wm * 64 + mt * 16 + g;
            const int n = n0 + wn * 32 + nt * 8 + 2 * t;
            float2 r0 = make_float2(acc[mt][nt][0], acc[mt][nt][1]);
            float2 r1 = make_float2(acc[mt][nt][2], acc[mt][nt][3]);
            if (HAS_BIAS) {
                const float bz0 = bias[n], bz1 = bias[n + 1];
                r0.x += bz0; r0.y += bz1;
                r1.x += bz0; r1.y += bz1;
            }
            *(float2*)&C[(size_t)m * N + n] = r0;
            *(float2*)&C[(size_t)(m + 8) * N + n] = r1;
        }
    }
}

#define QKV_STAGES 4
#define PROJ_STAGES 3
#define QKV_SMEM (QKV_STAGES * 2 * TILE_BYTES)    // 81920
#define PROJ_SMEM (PROJ_STAGES * 3 * TILE_BYTES)  // 92160

__global__ void __launch_bounds__(256, 2)
qkv_gemm_kernel() {
    gemm_body<QKV_N, 1, QKV_STAGES, false>(g_xh, nullptr, g_wqh, nullptr, g_qkv);
}

__global__ void __launch_bounds__(256, 2)
proj_gemm_kernel(const float* __restrict__ b_proj, float* __restrict__ out) {
    gemm_body<K_DIM, 2, PROJ_STAGES, true>(g_ah, g_al, g_wph, b_proj, out);
}

// ---------------------------------------------------------------------------
// Fused stripe attention + LePE; writes output pre-split to fp16 hi/lo.
// ---------------------------------------------------------------------------
__global__ void __launch_bounds__(256, 4)
attn_kernel(const float* __restrict__ lepe_h, const float* __restrict__ lepe_v) {
    __shared__ float qs[8][257];
    __shared__ float ks[8][257];
    __shared__ float vs[8][257];
    __shared__ float S[8][8][8];

    const int bidx = blockIdx.x;
    const int axis = bidx >> 12;
    const int rem  = bidx & 4095;
    const int b    = rem >> 9;
    const int r    = rem & 511;

    int tok_m[8];
    if (axis == 0) {
        const int s = r >> 6;
        const int w = r & 63;
        #pragma unroll
        for (int i = 0; i < 8; i++) tok_m[i] = (b << 12) + ((s * 8 + i) << 6) + w;
    } else {
        const int h = r >> 3;
        const int s = r & 7;
        #pragma unroll
        for (int i = 0; i < 8; i++) tok_m[i] = (b << 12) + (h << 6) + (s * 8 + i);
    }

    const int c_local = threadIdx.x;
    const int c = (axis << 8) + c_local;

    #pragma unroll
    for (int i = 0; i < 8; i++) {
        const float* base = &g_qkv[(size_t)tok_m[i] * QKV_N + c];
        qs[i][c_local] = base[0];
        ks[i][c_local] = base[512];
        vs[i][c_local] = base[1024];
    }
    __syncthreads();

    const float inv_scale = 0.17677669529663688f;  // 1/sqrt(32)
    #pragma unroll
    for (int e = 0; e < 2; e++) {
        const int idx = threadIdx.x + (e << 8);
        const int hh = idx >> 6;
        const int i = (idx >> 3) & 7;
        const int j = idx & 7;
        const int cbh = hh << 5;
        float sum = 0.f;
        #pragma unroll
        for (int d = 0; d < 32; d++) sum = fmaf(qs[i][cbh + d], ks[j][cbh + d], sum);
        S[hh][i][j] = sum * inv_scale;
    }
    __syncthreads();

    if (threadIdx.x < 64) {
        const int hh = threadIdx.x >> 3;
        const int i = threadIdx.x & 7;
        float* row = S[hh][i];
        float mx = row[0];
        #pragma unroll
        for (int j = 1; j < 8; j++) mx = fmaxf(mx, row[j]);
        float ex[8], sum = 0.f;
        #pragma unroll
        for (int j = 0; j < 8; j++) { ex[j] = __expf(row[j] - mx); sum += ex[j]; }
        const float inv = 1.f / sum;
        #pragma unroll
        for (int j = 0; j < 8; j++) row[j] = ex[j] * inv;
    }
    __syncthreads();

    const int head = c_local >> 5;
    const float* lw = (axis == 0) ? lepe_h : lepe_v;
    float wgt[9];
    #pragma unroll
    for (int tt = 0; tt < 9; tt++) wgt[tt] = lw[tt * 256 + c_local];

    #pragma unroll
    for (int i = 0; i < 8; i++) {
        float acc = 0.f;
        #pragma unroll
        for (int j = 0; j < 8; j++) acc = fmaf(S[head][i][j], vs[j][c_local], acc);

        const int m = tok_m[i];
        const int bb = m >> 12;
        const int h = (m >> 6) & 63;
        const int w = m & 63;
        float lep = 0.f;
        #pragma unroll
        for (int dh = -1; dh <= 1; dh++) {
            #pragma unroll
            for (int dw = -1; dw <= 1; dw++) {
                const int h2 = h + dh, w2 = w + dw;
                if (h2 >= 0 && h2 < 64 && w2 >= 0 && w2 < 64) {
                    const float vv = g_qkv[(size_t)((bb << 12) + (h2 << 6) + w2) * QKV_N + 1024 + c];
                    lep = fmaf(vv, wgt[(dh + 1) * 3 + (dw + 1)], lep);
                }
            }
        }
        const float o = acc + lep;
        const __half oh = __float2half_rn(o);
        g_ah[(size_t)m * K_DIM + c] = oh;
        g_al[(size_t)m * K_DIM + c] = __float2half_rn(o - __half2float(oh));
    }
}

// ---------------------------------------------------------------------------
extern "C" void kernel_launch(void* const* d_in, const int* in_sizes, int n_in,
                              void* d_out, int out_size) {
    (void)in_sizes; (void)n_in; (void)out_size;
    const float* x      = (const float*)d_in[0];  // (8, 4096, 512)
    const float* w_qkv  = (const float*)d_in[1];  // (1536, 512)
    const float* w_proj = (const float*)d_in[2];  // (512, 512)
    const float* b_proj = (const float*)d_in[3];  // (512,)
    const float* lepe_h = (const float*)d_in[4];  // (3,3,1,256)
    const float* lepe_v = (const float*)d_in[5];  // (3,3,1,256)
    float* out = (float*)d_out;                   // (8, 4096, 512)

    static bool attr_set = false;
    if (!attr_set) {
        cudaFuncSetAttribute(qkv_gemm_kernel, cudaFuncAttributeMaxDynamicSharedMemorySize, QKV_SMEM);
        cudaFuncSetAttribute(proj_gemm_kernel, cudaFuncAttributeMaxDynamicSharedMemorySize, PROJ_SMEM);
        attr_set = true;
    }

    __half* xh;  __half* wqh; __half* wph;
    cudaGetSymbolAddress((void**)&xh,  g_xh);
    cudaGetSymbolAddress((void**)&wqh, g_wqh);
    cudaGetSymbolAddress((void**)&wph, g_wph);

    dim3 blk(256);
    split_kernel<<<(M_TOT * K_DIM / 4 + 255) / 256, blk>>>(x, xh, nullptr, M_TOT * K_DIM / 4);
    split_kernel<<<(QKV_N * K_DIM / 4 + 255) / 256, blk>>>(w_qkv, wqh, nullptr, QKV_N * K_DIM / 4);
    split_kernel<<<(K_DIM * K_DIM / 4 + 255) / 256, blk>>>(w_proj, wph, nullptr, K_DIM * K_DIM / 4);

    qkv_gemm_kernel<<<dim3(QKV_N / 128, M_TOT / 128), blk, QKV_SMEM>>>();
    attn_kernel<<<8192, blk>>>(lepe_h, lepe_v);
    proj_gemm_kernel<<<dim3(K_DIM / 128, M_TOT / 128), blk, PROJ_SMEM>>>(b_proj, out);
}

// round 7
// speedup vs baseline: 3.6574x; 1.0502x over previous
#include <cuda_runtime.h>
#include <cuda_fp16.h>
#include <math.h>
#include <stdint.h>

// Problem constants (B=8, H=W=64, C=512, nh=16, hd=32, ss=8)
#define M_TOT 32768
#define K_DIM 512
#define QKV_N 1536

// Scratch (allocation-free rule: __device__ globals)
__device__ __align__(16) float  g_qkv[(size_t)M_TOT * QKV_N];   // q|k|v fp32 (attn input)
__device__ __align__(16) __half g_xh[(size_t)M_TOT * K_DIM];    // x hi
__device__ __align__(16) __half g_ah[(size_t)M_TOT * K_DIM];    // attn-out (fp16)
__device__ __align__(16) __half g_wqh[(size_t)QKV_N * K_DIM];   // w_qkv fp16
__device__ __align__(16) __half g_wph[(size_t)K_DIM * K_DIM];   // w_proj fp16

// ---------------------------------------------------------------------------
// Helpers
// ---------------------------------------------------------------------------
__device__ __forceinline__ uint32_t smem_u32(const void* p) {
    uint32_t a;
    asm("{ .reg .u64 t; cvta.to.shared.u64 t, %1; cvt.u32.u64 %0, t; }" : "=r"(a) : "l"(p));
    return a;
}
__device__ __forceinline__ void cp16(uint32_t dst, const void* src) {
    asm volatile("cp.async.cg.shared.global [%0], [%1], 16;"
                 :: "r"(dst), "l"(__cvta_generic_to_global(src)));
}
__device__ __forceinline__ void cp_commit() { asm volatile("cp.async.commit_group;"); }
template <int Nwait>
__device__ __forceinline__ void cp_wait() {
    asm volatile("cp.async.wait_group %0;" :: "n"(Nwait));
}
__device__ __forceinline__ void ldm4(uint32_t (&r)[4], uint32_t addr) {
    asm volatile("ldmatrix.sync.aligned.m8n8.x4.shared.b16 {%0,%1,%2,%3}, [%4];"
                 : "=r"(r[0]), "=r"(r[1]), "=r"(r[2]), "=r"(r[3]) : "r"(addr));
}
__device__ __forceinline__ void mma_f16(float (&d)[4], const uint32_t (&a)[4],
                                        uint32_t b0, uint32_t b1) {
    asm volatile(
        "mma.sync.aligned.m16n8k16.row.col.f32.f16.f16.f32 "
        "{%0,%1,%2,%3}, {%4,%5,%6,%7}, {%8,%9}, {%0,%1,%2,%3};"
        : "+f"(d[0]), "+f"(d[1]), "+f"(d[2]), "+f"(d[3])
        : "r"(a[0]), "r"(a[1]), "r"(a[2]), "r"(a[3]), "r"(b0), "r"(b1));
}

// ---------------------------------------------------------------------------
// fp32 -> fp16 convert (hi only)
// ---------------------------------------------------------------------------
__global__ void __launch_bounds__(256)
split_kernel(const float* __restrict__ src, __half* __restrict__ hi, int n4) {
    const int i = blockIdx.x * blockDim.x + threadIdx.x;
    if (i >= n4) return;
    const float4 f = ((const float4*)src)[i];
    ((__half2*)hi)[2 * i]     = __halves2half2(__float2half_rn(f.x), __float2half_rn(f.y));
    ((__half2*)hi)[2 * i + 1] = __halves2half2(__float2half_rn(f.z), __float2half_rn(f.w));
}

// ---------------------------------------------------------------------------
// fp16 tensor GEMM: C = Ah * Bh^T (+bias). BM=BN=128, BK=32, 8 warps
// (warp tile 64x32), 4-stage cp.async, ldmatrix with one-deep register
// double-buffering (prefetch tile t+1 before MMAs of tile t).
// Row stride 80B -> ldmatrix conflict-free.
// ---------------------------------------------------------------------------
#define BK 32
#define RS_B 80
#define TILE_BYTES (128 * RS_B)       // 10240
#define STAGE_BYTES (2 * TILE_BYTES)  // A | B
#define NSTAGE 4
#define GEMM_SMEM (NSTAGE * STAGE_BYTES)  // 81920
#define NCH (K_DIM / BK)              // 16

template <int N, bool HAS_BIAS>
__device__ __forceinline__ void gemm_body(const __half* __restrict__ Ah_g,
                                          const __half* __restrict__ Bh_g,
                                          const float* __restrict__ bias,
                                          float* __restrict__ C) {
    extern __shared__ __align__(16) char smem[];
    const uint32_t sbase = smem_u32(smem);

    const int tid = threadIdx.x;
    const int warp = tid >> 5;
    const int lane = tid & 31;
    const int wm = warp & 1;
    const int wn = warp >> 1;
    const int g = lane >> 2;
    const int t = lane & 3;

    const int m0 = blockIdx.y * 128;
    const int n0 = blockIdx.x * 128;

    const int crow = tid >> 1;
    const int cc = (tid & 1) * 2;
    const __half* a_src = Ah_g + (size_t)(m0 + crow) * K_DIM + cc * 8;
    const __half* b_src = Bh_g + (size_t)(n0 + crow) * K_DIM + cc * 8;
    const uint32_t cdst = sbase + crow * RS_B + cc * 16;

    const uint32_t aRow = (uint32_t)(wm * 64 + (lane & 15)) * RS_B + ((lane >> 4) << 4);
    const uint32_t bRow = (uint32_t)(wn * 32 + (lane & 7) + ((lane >> 4) << 3)) * RS_B +
                          (((lane >> 3) & 1) << 4);

    float acc[4][4][4];
    #pragma unroll
    for (int i = 0; i < 4; i++)
        #pragma unroll
        for (int j = 0; j < 4; j++)
            #pragma unroll
            for (int r = 0; r < 4; r++) acc[i][j][r] = 0.f;

    auto issue = [&](int ch) {
        if (ch < NCH) {
            const int ko = ch * BK;
            const uint32_t d = cdst + (uint32_t)(ch % NSTAGE) * STAGE_BYTES;
            cp16(d, a_src + ko);              cp16(d + 16, a_src + ko + 8);
            cp16(d + TILE_BYTES, b_src + ko); cp16(d + TILE_BYTES + 16, b_src + ko + 8);
        }
        cp_commit();
    };

    #pragma unroll
    for (int s = 0; s < NSTAGE - 1; s++) issue(s);

    for (int ch = 0; ch < NCH; ch++) {
        cp_wait<NSTAGE - 2>();
        __syncthreads();
        issue(ch + NSTAGE - 1);

        const uint32_t sA = sbase + (uint32_t)(ch % NSTAGE) * STAGE_BYTES;
        const uint32_t sB = sA + TILE_BYTES;

        // Fragment pipeline: prefetch next tile before current tile's MMAs.
        uint32_t bc0[4], bc1[4], bn0[4], bn1[4], a_cur[4], a_nxt[4];
        ldm4(bc0, sB + bRow);                       // ks0, n-tiles 0-1
        ldm4(bc1, sB + bRow + 16 * RS_B);           // ks0, n-tiles 2-3
        ldm4(a_cur, sA + aRow);                     // ks0, mt0

        #pragma unroll
        for (int ks = 0; ks < 2; ks++) {
            #pragma unroll
            for (int mt = 0; mt < 4; mt++) {
                if (mt < 3) {
                    ldm4(a_nxt, sA + aRow + (mt + 1) * 16 * RS_B + ks * 32);
                } else if (ks == 0) {
                    ldm4(bn0, sB + bRow + 32);              // ks1 B
                    ldm4(bn1, sB + bRow + 16 * RS_B + 32);
                    ldm4(a_nxt, sA + aRow + 32);            // ks1, mt0
                }
                mma_f16(acc[mt][0], a_cur, bc0[0], bc0[1]);
                mma_f16(acc[mt][1], a_cur, bc0[2], bc0[3]);
                mma_f16(acc[mt][2], a_cur, bc1[0], bc1[1]);
                mma_f16(acc[mt][3], a_cur, bc1[2], bc1[3]);
                if (ks < 1 || mt < 3) {
                    #pragma unroll
                    for (int r = 0; r < 4; r++) a_cur[r] = a_nxt[r];
                }
            }
            if (ks == 0) {
                #pragma unroll
                for (int r = 0; r < 4; r++) { bc0[r] = bn0[r]; bc1[r] = bn1[r]; }
            }
        }
    }

    #pragma unroll
    for (int mt = 0; mt < 4; mt++) {
        #pragma unroll
        for (int nt = 0; nt < 4; nt++) {
            const int m = m0 + wm * 64 + mt * 16 + g;
            const int n = n0 + wn * 32 + nt * 8 + 2 * t;
            float2 r0 = make_float2(acc[mt][nt][0], acc[mt][nt][1]);
            float2 r1 = make_float2(acc[mt][nt][2], acc[mt][nt][3]);
            if (HAS_BIAS) {
                const float bz0 = bias[n], bz1 = bias[n + 1];
                r0.x += bz0; r0.y += bz1;
                r1.x += bz0; r1.y += bz1;
            }
            *(float2*)&C[(size_t)m * N + n] = r0;
            *(float2*)&C[(size_t)(m + 8) * N + n] = r1;
        }
    }
}

__global__ void __launch_bounds__(256, 2)
qkv_gemm_kernel() {
    gemm_body<QKV_N, false>(g_xh, g_wqh, nullptr, g_qkv);
}

__global__ void __launch_bounds__(256, 2)
proj_gemm_kernel(const float* __restrict__ b_proj, float* __restrict__ out) {
    gemm_body<K_DIM, true>(g_ah, g_wph, b_proj, out);
}

// ---------------------------------------------------------------------------
// Fused stripe attention + LePE; writes output as fp16 (proj A operand).
// ---------------------------------------------------------------------------
__global__ void __launch_bounds__(256, 4)
attn_kernel(const float* __restrict__ lepe_h, const float* __restrict__ lepe_v) {
    __shared__ float qs[8][257];
    __shared__ float ks[8][257];
    __shared__ float vs[8][257];
    __shared__ float S[8][8][8];

    const int bidx = blockIdx.x;
    const int axis = bidx >> 12;
    const int rem  = bidx & 4095;
    const int b    = rem >> 9;
    const int r    = rem & 511;

    int tok_m[8];
    if (axis == 0) {
        const int s = r >> 6;
        const int w = r & 63;
        #pragma unroll
        for (int i = 0; i < 8; i++) tok_m[i] = (b << 12) + ((s * 8 + i) << 6) + w;
    } else {
        const int h = r >> 3;
        const int s = r & 7;
        #pragma unroll
        for (int i = 0; i < 8; i++) tok_m[i] = (b << 12) + (h << 6) + (s * 8 + i);
    }

    const int c_local = threadIdx.x;
    const int c = (axis << 8) + c_local;

    #pragma unroll
    for (int i = 0; i < 8; i++) {
        const float* base = &g_qkv[(size_t)tok_m[i] * QKV_N + c];
        qs[i][c_local] = base[0];
        ks[i][c_local] = base[512];
        vs[i][c_local] = base[1024];
    }
    __syncthreads();

    const float inv_scale = 0.17677669529663688f;  // 1/sqrt(32)
    #pragma unroll
    for (int e = 0; e < 2; e++) {
        const int idx = threadIdx.x + (e << 8);
        const int hh = idx >> 6;
        const int i = (idx >> 3) & 7;
        const int j = idx & 7;
        const int cbh = hh << 5;
        float sum = 0.f;
        #pragma unroll
        for (int d = 0; d < 32; d++) sum = fmaf(qs[i][cbh + d], ks[j][cbh + d], sum);
        S[hh][i][j] = sum * inv_scale;
    }
    __syncthreads();

    if (threadIdx.x < 64) {
        const int hh = threadIdx.x >> 3;
        const int i = threadIdx.x & 7;
        float* row = S[hh][i];
        float mx = row[0];
        #pragma unroll
        for (int j = 1; j < 8; j++) mx = fmaxf(mx, row[j]);
        float ex[8], sum = 0.f;
        #pragma unroll
        for (int j = 0; j < 8; j++) { ex[j] = __expf(row[j] - mx); sum += ex[j]; }
        const float inv = 1.f / sum;
        #pragma unroll
        for (int j = 0; j < 8; j++) row[j] = ex[j] * inv;
    }
    __syncthreads();

    const int head = c_local >> 5;
    const float* lw = (axis == 0) ? lepe_h : lepe_v;
    float wgt[9];
    #pragma unroll
    for (int tt = 0; tt < 9; tt++) wgt[tt] = lw[tt * 256 + c_local];

    #pragma unroll
    for (int i = 0; i < 8; i++) {
        float acc = 0.f;
        #pragma unroll
        for (int j = 0; j < 8; j++) acc = fmaf(S[head][i][j], vs[j][c_local], acc);

        const int m = tok_m[i];
        const int bb = m >> 12;
        const int h = (m >> 6) & 63;
        const int w = m & 63;
        float lep = 0.f;
        #pragma unroll
        for (int dh = -1; dh <= 1; dh++) {
            #pragma unroll
            for (int dw = -1; dw <= 1; dw++) {
                const int h2 = h + dh, w2 = w + dw;
                if (h2 >= 0 && h2 < 64 && w2 >= 0 && w2 < 64) {
                    const float vv = g_qkv[(size_t)((bb << 12) + (h2 << 6) + w2) * QKV_N + 1024 + c];
                    lep = fmaf(vv, wgt[(dh + 1) * 3 + (dw + 1)], lep);
                }
            }
        }
        g_ah[(size_t)m * K_DIM + c] = __float2half_rn(acc + lep);
    }
}

// ---------------------------------------------------------------------------
extern "C" void kernel_launch(void* const* d_in, const int* in_sizes, int n_in,
                              void* d_out, int out_size) {
    (void)in_sizes; (void)n_in; (void)out_size;
    const float* x      = (const float*)d_in[0];  // (8, 4096, 512)
    const float* w_qkv  = (const float*)d_in[1];  // (1536, 512)
    const float* w_proj = (const float*)d_in[2];  // (512, 512)
    const float* b_proj = (const float*)d_in[3];  // (512,)
    const float* lepe_h = (const float*)d_in[4];  // (3,3,1,256)
    const float* lepe_v = (const float*)d_in[5];  // (3,3,1,256)
    float* out = (float*)d_out;                   // (8, 4096, 512)

    static bool attr_set = false;
    if (!attr_set) {
        cudaFuncSetAttribute(qkv_gemm_kernel, cudaFuncAttributeMaxDynamicSharedMemorySize, GEMM_SMEM);
        cudaFuncSetAttribute(proj_gemm_kernel, cudaFuncAttributeMaxDynamicSharedMemorySize, GEMM_SMEM);
        attr_set = true;
    }

    __half* xh;  __half* wqh; __half* wph;
    cudaGetSymbolAddress((void**)&xh,  g_xh);
    cudaGetSymbolAddress((void**)&wqh, g_wqh);
    cudaGetSymbolAddress((void**)&wph, g_wph);

    dim3 blk(256);
    split_kernel<<<(M_TOT * K_DIM / 4 + 255) / 256, blk>>>(x, xh, M_TOT * K_DIM / 4);
    split_kernel<<<(QKV_N * K_DIM / 4 + 255) / 256, blk>>>(w_qkv, wqh, QKV_N * K_DIM / 4);
    split_kernel<<<(K_DIM * K_DIM / 4 + 255) / 256, blk>>>(w_proj, wph, K_DIM * K_DIM / 4);

    qkv_gemm_kernel<<<dim3(QKV_N / 128, M_TOT / 128), blk, GEMM_SMEM>>>();
    attn_kernel<<<8192, blk>>>(lepe_h, lepe_v);
    proj_gemm_kernel<<<dim3(K_DIM / 128, M_TOT / 128), blk, GEMM_SMEM>>>(b_proj, out);
}